// round 3
// baseline (speedup 1.0000x reference)
#include <cuda_runtime.h>
#include <cuda_bf16.h>
#include <math.h>

#define NN 50000
#define NE 800000
#define NG 128
#define DD 128
#define NL 4

// Scratch (allocation-free rule: __device__ globals)
__device__ float g_bufA[NN * DD];
__device__ float g_bufB[NN * DD];
__device__ int   g_cnt[NG];
__device__ int   g_start[NG];

// ---------------------------------------------------------------------------
// small helpers
// ---------------------------------------------------------------------------
__global__ void k_zero_cnt() {
    if (threadIdx.x < NG) g_cnt[threadIdx.x] = 0;
}

__global__ void k_count(const int* __restrict__ batch) {
    int i = blockIdx.x * blockDim.x + threadIdx.x;
    if (i < NN) {
        int g = batch[i];
        g = max(0, min(g, NG - 1));
        atomicAdd(&g_cnt[g], 1);
    }
}

__global__ void k_scan() {
    if (threadIdx.x == 0) {
        int acc = 0;
        for (int g = 0; g < NG; g++) { g_start[g] = acc; acc += g_cnt[g]; }
    }
}

__global__ void k_copy(const float4* __restrict__ src, float4* __restrict__ dst, int n4) {
    int i = blockIdx.x * blockDim.x + threadIdx.x;
    if (i < n4) dst[i] = src[i];
}

// ---------------------------------------------------------------------------
// Edge scatter: agg[dst] += h[src], one warp per edge, float4 gather
// edge_index is int32 (JAX x64-disabled downcasts int64 -> int32).
// ---------------------------------------------------------------------------
__global__ __launch_bounds__(256) void k_scatter(const float4* __restrict__ h,
                                                 float* __restrict__ agg,
                                                 const int* __restrict__ ei) {
    int w = (blockIdx.x * blockDim.x + threadIdx.x) >> 5;
    if (w >= NE) return;
    int lane = threadIdx.x & 31;
    int s = ei[w];
    int d = ei[NE + w];
    s = max(0, min(s, NN - 1));
    d = max(0, min(d, NN - 1));
    float4 v = h[s * 32 + lane];
    float* p = agg + (size_t)d * DD + lane * 4;
    atomicAdd(p + 0, v.x);
    atomicAdd(p + 1, v.y);
    atomicAdd(p + 2, v.z);
    atomicAdd(p + 3, v.w);
}

// ---------------------------------------------------------------------------
// Fused GEMM + bias + ReLU:  out[M,128] = relu(A[M,128] @ W[128,128] + b)
// Block: 256 threads, 64-row tile. Thread tile: 8 rows x 4 cols.
// ---------------------------------------------------------------------------
__global__ __launch_bounds__(256) void k_gemm_relu(const float* __restrict__ A,
                                                   const float* __restrict__ W,
                                                   const float* __restrict__ bias,
                                                   float* __restrict__ out, int M) {
    __shared__ float As[64 * 128];
    int tid = threadIdx.x;
    int block_row = blockIdx.x * 64;

    const float4* A4 = (const float4*)(A + (size_t)block_row * DD);
    float4* As4 = (float4*)As;
#pragma unroll
    for (int i = 0; i < 8; i++) {
        int idx = tid + i * 256;       // 0..2047
        int r = idx >> 5;              // row within tile
        float4 v = make_float4(0.f, 0.f, 0.f, 0.f);
        if (block_row + r < M) v = A4[idx];
        As4[idx] = v;
    }
    __syncthreads();

    int tx = tid & 31;   // column group (4 cols)
    int ty = tid >> 5;   // row group (8 rows)

    float acc[8][4];
#pragma unroll
    for (int i = 0; i < 8; i++)
#pragma unroll
        for (int j = 0; j < 4; j++) acc[i][j] = 0.f;

    const float4* W4 = (const float4*)W;
#pragma unroll 8
    for (int k = 0; k < 128; k++) {
        float4 w = W4[k * 32 + tx];
#pragma unroll
        for (int i = 0; i < 8; i++) {
            float a = As[(ty * 8 + i) * 128 + k];   // warp-broadcast LDS
            acc[i][0] += a * w.x;
            acc[i][1] += a * w.y;
            acc[i][2] += a * w.z;
            acc[i][3] += a * w.w;
        }
    }

    float4 bb = ((const float4*)bias)[tx];
#pragma unroll
    for (int i = 0; i < 8; i++) {
        int row = block_row + ty * 8 + i;
        if (row < M) {
            float4 o;
            o.x = fmaxf(acc[i][0] + bb.x, 0.f);
            o.y = fmaxf(acc[i][1] + bb.y, 0.f);
            o.z = fmaxf(acc[i][2] + bb.z, 0.f);
            o.w = fmaxf(acc[i][3] + bb.w, 0.f);
            ((float4*)out)[(size_t)row * 32 + tx] = o;
        }
    }
}

// ---------------------------------------------------------------------------
// GraphNorm + ReLU. batch is sorted -> graph g owns rows [start, start+cnt).
// One block (128 threads = one per feature) per graph; 3 coalesced passes.
// ---------------------------------------------------------------------------
__global__ __launch_bounds__(128) void k_gnorm(const float* __restrict__ in,
                                               float* __restrict__ out,
                                               const float* __restrict__ w,
                                               const float* __restrict__ b,
                                               const float* __restrict__ ms) {
    int g = blockIdx.x, d = threadIdx.x;
    int st = g_start[g], cnt = g_cnt[g];
    if (cnt == 0) return;
    float inv_n = 1.0f / (float)cnt;

    float sum = 0.f;
    for (int r = st; r < st + cnt; r++) sum += in[(size_t)r * DD + d];
    float mean = sum * inv_n * ms[d];   // mean * mean_scale

    float v = 0.f;
    for (int r = st; r < st + cnt; r++) {
        float o = in[(size_t)r * DD + d] - mean;
        v += o * o;
    }
    float scale = w[d] * rsqrtf(v * inv_n + 1e-5f);
    float bd = b[d];

    for (int r = st; r < st + cnt; r++) {
        float o = in[(size_t)r * DD + d] - mean;
        out[(size_t)r * DD + d] = fmaxf(o * scale + bd, 0.f);
    }
}

// ---------------------------------------------------------------------------
// Head: sum-pool per graph + MLP(relu,relu) + final 128x10 + log_softmax
// One block per graph, 128 threads.
// ---------------------------------------------------------------------------
__global__ __launch_bounds__(128) void k_head(const float* __restrict__ h,
                                              const float* __restrict__ fw1,
                                              const float* __restrict__ fb1,
                                              const float* __restrict__ fw2,
                                              const float* __restrict__ fb2,
                                              const float* __restrict__ fw3,
                                              const float* __restrict__ fb3,
                                              float* __restrict__ out) {
    int g = blockIdx.x, d = threadIdx.x;
    __shared__ float s0[128], s1[128], s2[128], lg[10];

    int st = g_start[g], cnt = g_cnt[g];
    float sum = 0.f;
    for (int r = st; r < st + cnt; r++) sum += h[(size_t)r * DD + d];
    s0[d] = sum;
    __syncthreads();

    float acc = fb1[d];
    for (int k = 0; k < 128; k++) acc += s0[k] * fw1[k * 128 + d];
    s1[d] = fmaxf(acc, 0.f);
    __syncthreads();

    acc = fb2[d];
    for (int k = 0; k < 128; k++) acc += s1[k] * fw2[k * 128 + d];
    s2[d] = fmaxf(acc, 0.f);
    __syncthreads();

    if (d < 10) {
        float a = fb3[d];
        for (int k = 0; k < 128; k++) a += s2[k] * fw3[k * 10 + d];
        lg[d] = a;
    }
    __syncthreads();

    if (d == 0) {
        float m = lg[0];
        for (int c = 1; c < 10; c++) m = fmaxf(m, lg[c]);
        float s = 0.f;
        for (int c = 0; c < 10; c++) s += expf(lg[c] - m);
        float lse = m + logf(s);
        for (int c = 0; c < 10; c++) out[g * 10 + c] = lg[c] - lse;
    }
}

// ---------------------------------------------------------------------------
// Launch
// ---------------------------------------------------------------------------
extern "C" void kernel_launch(void* const* d_in, const int* in_sizes, int n_in,
                              void* d_out, int out_size) {
    const float* x      = (const float*)d_in[0];
    const float* gin_w1 = (const float*)d_in[1];
    const float* gin_b1 = (const float*)d_in[2];
    const float* gin_w2 = (const float*)d_in[3];
    const float* gin_b2 = (const float*)d_in[4];
    const float* gn_w   = (const float*)d_in[5];
    const float* gn_b   = (const float*)d_in[6];
    const float* gn_s   = (const float*)d_in[7];
    const float* fw1    = (const float*)d_in[8];
    const float* fb1    = (const float*)d_in[9];
    const float* fw2    = (const float*)d_in[10];
    const float* fb2    = (const float*)d_in[11];
    const float* fw3    = (const float*)d_in[12];
    const float* fb3    = (const float*)d_in[13];
    const int* ei    = (const int*)d_in[14];   // int32 (JAX x64 disabled)
    const int* batch = (const int*)d_in[15];   // int32
    float* out = (float*)d_out;

    float* bufA;  cudaGetSymbolAddress((void**)&bufA, g_bufA);
    float* bufB;  cudaGetSymbolAddress((void**)&bufB, g_bufB);

    const int n4 = NN * DD / 4;           // 1.6M float4
    const int copy_grid = (n4 + 255) / 256;
    const int gemm_grid = (NN + 63) / 64;
    const int scat_grid = (NE * 32 + 255) / 256;   // one warp per edge

    // graph ranges
    k_zero_cnt<<<1, 128>>>();
    k_count<<<(NN + 255) / 256, 256>>>(batch);
    k_scan<<<1, 32>>>();

    // h <- x
    k_copy<<<copy_grid, 256>>>((const float4*)x, (float4*)bufA, n4);

    for (int l = 0; l < NL; l++) {
        // agg <- h ;  agg[dst] += h[src]
        k_copy<<<copy_grid, 256>>>((const float4*)bufA, (float4*)bufB, n4);
        k_scatter<<<scat_grid, 256>>>((const float4*)bufA, bufB, ei);
        // h' = relu(agg @ W1 + b1)
        k_gemm_relu<<<gemm_grid, 256>>>(bufB, gin_w1 + l * 128 * 128,
                                        gin_b1 + l * 128, bufA, NN);
        // h'' = relu(h' @ W2 + b2)
        k_gemm_relu<<<gemm_grid, 256>>>(bufA, gin_w2 + l * 128 * 128,
                                        gin_b2 + l * 128, bufB, NN);
        // GraphNorm + relu
        k_gnorm<<<NG, 128>>>(bufB, bufA, gn_w + l * 128, gn_b + l * 128,
                             gn_s + l * 128);
    }

    k_head<<<NG, 128>>>(bufA, fw1, fb1, fw2, fb2, fw3, fb3, out);
}

// round 4
// speedup vs baseline: 1.1378x; 1.1378x over previous
#include <cuda_runtime.h>
#include <cuda_bf16.h>
#include <math.h>

#define NN 50000
#define NE 800000
#define NG 128
#define DD 128
#define NL 4

__device__ float g_bufA[NN * DD];
__device__ float g_bufB[NN * DD];
__device__ int   g_cnt[NG];
__device__ int   g_start[NG];

// ---------------------------------------------------------------------------
__global__ void k_zero_cnt() {
    if (threadIdx.x < NG) g_cnt[threadIdx.x] = 0;
}

__global__ void k_count(const int* __restrict__ batch) {
    int i = blockIdx.x * blockDim.x + threadIdx.x;
    if (i < NN) {
        int g = batch[i];
        g = max(0, min(g, NG - 1));
        atomicAdd(&g_cnt[g], 1);
    }
}

__global__ void k_scan() {
    if (threadIdx.x == 0) {
        int acc = 0;
        for (int g = 0; g < NG; g++) { g_start[g] = acc; acc += g_cnt[g]; }
    }
}

__global__ void k_copy(const float4* __restrict__ src, float4* __restrict__ dst, int n4) {
    int i = blockIdx.x * blockDim.x + threadIdx.x;
    if (i < n4) dst[i] = src[i];
}

// ---------------------------------------------------------------------------
// Edge scatter: agg[dst] += h[src]. One warp per edge, float4 gather,
// single red.global.add.v4.f32 per lane (sm_90+): 1 REDG.128 warp-instr/edge
// instead of 4 REDG.32 -> 4x less atomic issue pressure.
// ---------------------------------------------------------------------------
__global__ __launch_bounds__(256) void k_scatter(const float4* __restrict__ h,
                                                 float* __restrict__ agg,
                                                 const int* __restrict__ ei) {
    int w = (blockIdx.x * blockDim.x + threadIdx.x) >> 5;
    if (w >= NE) return;
    int lane = threadIdx.x & 31;
    int s = ei[w];
    int d = ei[NE + w];
    s = max(0, min(s, NN - 1));
    d = max(0, min(d, NN - 1));
    float4 v = h[s * 32 + lane];
    float* p = agg + (size_t)d * DD + lane * 4;
    asm volatile("red.global.add.v4.f32 [%0], {%1, %2, %3, %4};"
                 :: "l"(p), "f"(v.x), "f"(v.y), "f"(v.z), "f"(v.w)
                 : "memory");
}

// ---------------------------------------------------------------------------
// Fused GEMM + bias + ReLU:  out[M,128] = relu(A[M,128] @ W[128,128] + b)
// 256 threads, 64-row tile, 8x4 thread tile. FFMA-floor bound (~16k cyc/blk).
// ---------------------------------------------------------------------------
__global__ __launch_bounds__(256) void k_gemm_relu(const float* __restrict__ A,
                                                   const float* __restrict__ W,
                                                   const float* __restrict__ bias,
                                                   float* __restrict__ out, int M) {
    __shared__ float As[64 * 128];
    int tid = threadIdx.x;
    int block_row = blockIdx.x * 64;

    const float4* A4 = (const float4*)(A + (size_t)block_row * DD);
    float4* As4 = (float4*)As;
#pragma unroll
    for (int i = 0; i < 8; i++) {
        int idx = tid + i * 256;
        int r = idx >> 5;
        float4 v = make_float4(0.f, 0.f, 0.f, 0.f);
        if (block_row + r < M) v = A4[idx];
        As4[idx] = v;
    }
    __syncthreads();

    int tx = tid & 31;
    int ty = tid >> 5;

    float acc[8][4];
#pragma unroll
    for (int i = 0; i < 8; i++)
#pragma unroll
        for (int j = 0; j < 4; j++) acc[i][j] = 0.f;

    const float4* W4 = (const float4*)W;
#pragma unroll 8
    for (int k = 0; k < 128; k++) {
        float4 w = W4[k * 32 + tx];
#pragma unroll
        for (int i = 0; i < 8; i++) {
            float a = As[(ty * 8 + i) * 128 + k];
            acc[i][0] += a * w.x;
            acc[i][1] += a * w.y;
            acc[i][2] += a * w.z;
            acc[i][3] += a * w.w;
        }
    }

    float4 bb = ((const float4*)bias)[tx];
#pragma unroll
    for (int i = 0; i < 8; i++) {
        int row = block_row + ty * 8 + i;
        if (row < M) {
            float4 o;
            o.x = fmaxf(acc[i][0] + bb.x, 0.f);
            o.y = fmaxf(acc[i][1] + bb.y, 0.f);
            o.z = fmaxf(acc[i][2] + bb.z, 0.f);
            o.w = fmaxf(acc[i][3] + bb.w, 0.f);
            ((float4*)out)[(size_t)row * 32 + tx] = o;
        }
    }
}

// ---------------------------------------------------------------------------
// GraphNorm + ReLU. 512 threads/block: 4 row-slices per feature for MLP,
// cross-slice reduction in smem. batch sorted -> contiguous row ranges.
// ---------------------------------------------------------------------------
__global__ __launch_bounds__(512) void k_gnorm(const float* __restrict__ in,
                                               float* __restrict__ out,
                                               const float* __restrict__ w,
                                               const float* __restrict__ b,
                                               const float* __restrict__ ms) {
    __shared__ float red[4][128];
    int g = blockIdx.x;
    int d = threadIdx.x & 127;
    int sub = threadIdx.x >> 7;          // 0..3
    int st = g_start[g], cnt = g_cnt[g];
    if (cnt == 0) return;
    float inv_n = 1.0f / (float)cnt;

    float sum = 0.f;
    for (int r = st + sub; r < st + cnt; r += 4) sum += in[(size_t)r * DD + d];
    red[sub][d] = sum;
    __syncthreads();
    float mean = (red[0][d] + red[1][d] + red[2][d] + red[3][d]) * inv_n * ms[d];
    __syncthreads();

    float v = 0.f;
    for (int r = st + sub; r < st + cnt; r += 4) {
        float o = in[(size_t)r * DD + d] - mean;
        v += o * o;
    }
    red[sub][d] = v;
    __syncthreads();
    v = red[0][d] + red[1][d] + red[2][d] + red[3][d];
    float scale = w[d] * rsqrtf(v * inv_n + 1e-5f);
    float bd = b[d];

    for (int r = st + sub; r < st + cnt; r += 4) {
        float o = in[(size_t)r * DD + d] - mean;
        out[(size_t)r * DD + d] = fmaxf(o * scale + bd, 0.f);
    }
}

// ---------------------------------------------------------------------------
// Head: sum-pool per graph (512 threads, 4 row-slices) + MLP + log_softmax
// ---------------------------------------------------------------------------
__global__ __launch_bounds__(512) void k_head(const float* __restrict__ h,
                                              const float* __restrict__ fw1,
                                              const float* __restrict__ fb1,
                                              const float* __restrict__ fw2,
                                              const float* __restrict__ fb2,
                                              const float* __restrict__ fw3,
                                              const float* __restrict__ fb3,
                                              float* __restrict__ out) {
    int g = blockIdx.x;
    int d = threadIdx.x & 127;
    int sub = threadIdx.x >> 7;
    __shared__ float red[4][128];
    __shared__ float s0[128], s1[128], s2[128], lg[10];

    int st = g_start[g], cnt = g_cnt[g];
    float sum = 0.f;
    for (int r = st + sub; r < st + cnt; r += 4) sum += h[(size_t)r * DD + d];
    red[sub][d] = sum;
    __syncthreads();
    if (sub == 0) s0[d] = red[0][d] + red[1][d] + red[2][d] + red[3][d];
    __syncthreads();

    if (sub == 0) {
        float acc = fb1[d];
        for (int k = 0; k < 128; k++) acc += s0[k] * fw1[k * 128 + d];
        s1[d] = fmaxf(acc, 0.f);
    }
    __syncthreads();

    if (sub == 0) {
        float acc = fb2[d];
        for (int k = 0; k < 128; k++) acc += s1[k] * fw2[k * 128 + d];
        s2[d] = fmaxf(acc, 0.f);
    }
    __syncthreads();

    if (sub == 0 && d < 10) {
        float a = fb3[d];
        for (int k = 0; k < 128; k++) a += s2[k] * fw3[k * 10 + d];
        lg[d] = a;
    }
    __syncthreads();

    if (threadIdx.x == 0) {
        float m = lg[0];
        for (int c = 1; c < 10; c++) m = fmaxf(m, lg[c]);
        float s = 0.f;
        for (int c = 0; c < 10; c++) s += expf(lg[c] - m);
        float lse = m + logf(s);
        for (int c = 0; c < 10; c++) out[g * 10 + c] = lg[c] - lse;
    }
}

// ---------------------------------------------------------------------------
extern "C" void kernel_launch(void* const* d_in, const int* in_sizes, int n_in,
                              void* d_out, int out_size) {
    const float* x      = (const float*)d_in[0];
    const float* gin_w1 = (const float*)d_in[1];
    const float* gin_b1 = (const float*)d_in[2];
    const float* gin_w2 = (const float*)d_in[3];
    const float* gin_b2 = (const float*)d_in[4];
    const float* gn_w   = (const float*)d_in[5];
    const float* gn_b   = (const float*)d_in[6];
    const float* gn_s   = (const float*)d_in[7];
    const float* fw1    = (const float*)d_in[8];
    const float* fb1    = (const float*)d_in[9];
    const float* fw2    = (const float*)d_in[10];
    const float* fb2    = (const float*)d_in[11];
    const float* fw3    = (const float*)d_in[12];
    const float* fb3    = (const float*)d_in[13];
    const int* ei    = (const int*)d_in[14];   // int32 (JAX x64 disabled)
    const int* batch = (const int*)d_in[15];   // int32
    float* out = (float*)d_out;

    float* bufA;  cudaGetSymbolAddress((void**)&bufA, g_bufA);
    float* bufB;  cudaGetSymbolAddress((void**)&bufB, g_bufB);

    const int n4 = NN * DD / 4;
    const int copy_grid = (n4 + 255) / 256;
    const int gemm_grid = (NN + 63) / 64;
    const int scat_grid = (NE * 32 + 255) / 256;

    k_zero_cnt<<<1, 128>>>();
    k_count<<<(NN + 255) / 256, 256>>>(batch);
    k_scan<<<1, 32>>>();

    k_copy<<<copy_grid, 256>>>((const float4*)x, (float4*)bufA, n4);

    for (int l = 0; l < NL; l++) {
        k_copy<<<copy_grid, 256>>>((const float4*)bufA, (float4*)bufB, n4);
        k_scatter<<<scat_grid, 256>>>((const float4*)bufA, bufB, ei);
        k_gemm_relu<<<gemm_grid, 256>>>(bufB, gin_w1 + l * 128 * 128,
                                        gin_b1 + l * 128, bufA, NN);
        k_gemm_relu<<<gemm_grid, 256>>>(bufA, gin_w2 + l * 128 * 128,
                                        gin_b2 + l * 128, bufB, NN);
        k_gnorm<<<NG, 512>>>(bufB, bufA, gn_w + l * 128, gn_b + l * 128,
                             gn_s + l * 128);
    }

    k_head<<<NG, 512>>>(bufA, fw1, fb1, fw2, fb2, fw3, fb3, out);
}

// round 5
// speedup vs baseline: 1.9784x; 1.7388x over previous
#include <cuda_runtime.h>
#include <cuda_bf16.h>
#include <math.h>

#define NN 50000
#define NE 800000
#define NG 128
#define DD 128
#define NL 4

__device__ float g_bufA[NN * DD];
__device__ float g_bufB[NN * DD];
__device__ int   g_cnt[NG];
__device__ int   g_start[NG];
__device__ int   g_deg[NN];
__device__ int   g_row[NN + 1];
__device__ int   g_cur[NN];
__device__ int   g_srcs[NE];

// ---------------------------------------------------------------------------
// CSR build
// ---------------------------------------------------------------------------
__global__ void k_zero() {
    int i = blockIdx.x * blockDim.x + threadIdx.x;
    if (i < NN) g_deg[i] = 0;
    if (i < NG) g_cnt[i] = 0;
}

__global__ void k_hist(const int* __restrict__ ei, const int* __restrict__ batch) {
    int i = blockIdx.x * blockDim.x + threadIdx.x;
    if (i < NE) {
        int d = ei[NE + i];
        d = max(0, min(d, NN - 1));
        atomicAdd(&g_deg[d], 1);
    }
    if (i < NN) {
        int g = batch[i];
        g = max(0, min(g, NG - 1));
        atomicAdd(&g_cnt[g], 1);
    }
}

// single-block scan: node-degree prefix sum + graph-count prefix sum
__global__ __launch_bounds__(1024) void k_scan() {
    const int T = 1024;
    const int PER = (NN + T - 1) / T;   // 49
    __shared__ int ssum[T];
    int t = threadIdx.x;
    int lo = t * PER, hi = min(lo + PER, NN);

    int s = 0;
    for (int i = lo; i < hi; i++) s += g_deg[i];
    ssum[t] = s;
    __syncthreads();
    for (int off = 1; off < T; off <<= 1) {
        int v = (t >= off) ? ssum[t - off] : 0;
        __syncthreads();
        ssum[t] += v;
        __syncthreads();
    }
    int run = ssum[t] - s;              // exclusive base
    for (int i = lo; i < hi; i++) {
        g_row[i] = run;
        g_cur[i] = run;
        run += g_deg[i];
    }
    if (t == T - 1) g_row[NN] = ssum[T - 1];
    if (t == 0) {
        int acc = 0;
        for (int g = 0; g < NG; g++) { g_start[g] = acc; acc += g_cnt[g]; }
    }
}

__global__ void k_fill(const int* __restrict__ ei) {
    int i = blockIdx.x * blockDim.x + threadIdx.x;
    if (i >= NE) return;
    int s = ei[i];
    int d = ei[NE + i];
    s = max(0, min(s, NN - 1));
    d = max(0, min(d, NN - 1));
    int slot = atomicAdd(&g_cur[d], 1);
    g_srcs[slot] = s;
}

// ---------------------------------------------------------------------------
// CSR gather: out[n] = h[n] + sum_{src in csr[n]} h[src]
// One warp per node; 4-way unrolled gather for MLP.
// ---------------------------------------------------------------------------
__global__ __launch_bounds__(256) void k_gather(const float4* __restrict__ h,
                                                float4* __restrict__ out) {
    int n = (blockIdx.x * blockDim.x + threadIdx.x) >> 5;
    if (n >= NN) return;
    int lane = threadIdx.x & 31;

    float4 a0 = h[n * 32 + lane];
    float4 a1 = make_float4(0.f, 0.f, 0.f, 0.f);
    float4 a2 = a1, a3 = a1;

    int e = g_row[n], end = g_row[n + 1];
    for (; e + 3 < end; e += 4) {
        int s0 = g_srcs[e], s1 = g_srcs[e + 1], s2 = g_srcs[e + 2], s3 = g_srcs[e + 3];
        float4 v0 = h[s0 * 32 + lane];
        float4 v1 = h[s1 * 32 + lane];
        float4 v2 = h[s2 * 32 + lane];
        float4 v3 = h[s3 * 32 + lane];
        a0.x += v0.x; a0.y += v0.y; a0.z += v0.z; a0.w += v0.w;
        a1.x += v1.x; a1.y += v1.y; a1.z += v1.z; a1.w += v1.w;
        a2.x += v2.x; a2.y += v2.y; a2.z += v2.z; a2.w += v2.w;
        a3.x += v3.x; a3.y += v3.y; a3.z += v3.z; a3.w += v3.w;
    }
    for (; e < end; e++) {
        int s0 = g_srcs[e];
        float4 v0 = h[s0 * 32 + lane];
        a0.x += v0.x; a0.y += v0.y; a0.z += v0.z; a0.w += v0.w;
    }
    float4 r;
    r.x = (a0.x + a1.x) + (a2.x + a3.x);
    r.y = (a0.y + a1.y) + (a2.y + a3.y);
    r.z = (a0.z + a1.z) + (a2.z + a3.z);
    r.w = (a0.w + a1.w) + (a2.w + a3.w);
    out[n * 32 + lane] = r;
}

// ---------------------------------------------------------------------------
// Fused GEMM + bias + ReLU:  out[M,128] = relu(A[M,128] @ W[128,128] + b)
// ---------------------------------------------------------------------------
__global__ __launch_bounds__(256) void k_gemm_relu(const float* __restrict__ A,
                                                   const float* __restrict__ W,
                                                   const float* __restrict__ bias,
                                                   float* __restrict__ out, int M) {
    __shared__ float As[64 * 128];
    int tid = threadIdx.x;
    int block_row = blockIdx.x * 64;

    const float4* A4 = (const float4*)(A + (size_t)block_row * DD);
    float4* As4 = (float4*)As;
#pragma unroll
    for (int i = 0; i < 8; i++) {
        int idx = tid + i * 256;
        int r = idx >> 5;
        float4 v = make_float4(0.f, 0.f, 0.f, 0.f);
        if (block_row + r < M) v = A4[idx];
        As4[idx] = v;
    }
    __syncthreads();

    int tx = tid & 31;
    int ty = tid >> 5;

    float acc[8][4];
#pragma unroll
    for (int i = 0; i < 8; i++)
#pragma unroll
        for (int j = 0; j < 4; j++) acc[i][j] = 0.f;

    const float4* W4 = (const float4*)W;
#pragma unroll 8
    for (int k = 0; k < 128; k++) {
        float4 w = W4[k * 32 + tx];
#pragma unroll
        for (int i = 0; i < 8; i++) {
            float a = As[(ty * 8 + i) * 128 + k];
            acc[i][0] += a * w.x;
            acc[i][1] += a * w.y;
            acc[i][2] += a * w.z;
            acc[i][3] += a * w.w;
        }
    }

    float4 bb = ((const float4*)bias)[tx];
#pragma unroll
    for (int i = 0; i < 8; i++) {
        int row = block_row + ty * 8 + i;
        if (row < M) {
            float4 o;
            o.x = fmaxf(acc[i][0] + bb.x, 0.f);
            o.y = fmaxf(acc[i][1] + bb.y, 0.f);
            o.z = fmaxf(acc[i][2] + bb.z, 0.f);
            o.w = fmaxf(acc[i][3] + bb.w, 0.f);
            ((float4*)out)[(size_t)row * 32 + tx] = o;
        }
    }
}

// ---------------------------------------------------------------------------
// GraphNorm + ReLU, fused mean/var (sum + sumsq in one pass), 8-way MLP unroll.
// 512 threads: feature d = tid&127, row-slice sub = tid>>7 (stride 4).
// ---------------------------------------------------------------------------
__global__ __launch_bounds__(512) void k_gnorm(const float* __restrict__ in,
                                               float* __restrict__ out,
                                               const float* __restrict__ w,
                                               const float* __restrict__ b,
                                               const float* __restrict__ ms) {
    __shared__ float redA[4][128];
    __shared__ float redB[4][128];
    int g = blockIdx.x;
    int d = threadIdx.x & 127;
    int sub = threadIdx.x >> 7;
    int st = g_start[g], cnt = g_cnt[g];
    if (cnt == 0) return;
    int end = st + cnt;

    float s1 = 0.f, s2 = 0.f;
    int r = st + sub;
    for (; r + 28 < end; r += 32) {
        float v0 = in[(size_t)(r)      * DD + d];
        float v1 = in[(size_t)(r + 4)  * DD + d];
        float v2 = in[(size_t)(r + 8)  * DD + d];
        float v3 = in[(size_t)(r + 12) * DD + d];
        float v4 = in[(size_t)(r + 16) * DD + d];
        float v5 = in[(size_t)(r + 20) * DD + d];
        float v6 = in[(size_t)(r + 24) * DD + d];
        float v7 = in[(size_t)(r + 28) * DD + d];
        s1 += ((v0 + v1) + (v2 + v3)) + ((v4 + v5) + (v6 + v7));
        s2 += ((v0 * v0 + v1 * v1) + (v2 * v2 + v3 * v3)) +
              ((v4 * v4 + v5 * v5) + (v6 * v6 + v7 * v7));
    }
    for (; r < end; r += 4) {
        float v = in[(size_t)r * DD + d];
        s1 += v;
        s2 += v * v;
    }
    redA[sub][d] = s1;
    redB[sub][d] = s2;
    __syncthreads();
    float S1 = (redA[0][d] + redA[1][d]) + (redA[2][d] + redA[3][d]);
    float S2 = (redB[0][d] + redB[1][d]) + (redB[2][d] + redB[3][d]);

    float inv_n = 1.0f / (float)cnt;
    float mh = S1 * inv_n;          // E[h]
    float m  = mh * ms[d];          // mean * mean_scale
    float var = S2 * inv_n - 2.f * m * mh + m * m;   // E[(h-m)^2]
    float sc = w[d] * rsqrtf(var + 1e-5f);
    float bd = b[d];

#pragma unroll 8
    for (r = st + sub; r < end; r += 4) {
        float v = in[(size_t)r * DD + d];
        out[(size_t)r * DD + d] = fmaxf((v - m) * sc + bd, 0.f);
    }
}

// ---------------------------------------------------------------------------
// Head: sum-pool per graph (4-way unrolled) + MLP + log_softmax
// ---------------------------------------------------------------------------
__global__ __launch_bounds__(512) void k_head(const float* __restrict__ h,
                                              const float* __restrict__ fw1,
                                              const float* __restrict__ fb1,
                                              const float* __restrict__ fw2,
                                              const float* __restrict__ fb2,
                                              const float* __restrict__ fw3,
                                              const float* __restrict__ fb3,
                                              float* __restrict__ out) {
    int g = blockIdx.x;
    int d = threadIdx.x & 127;
    int sub = threadIdx.x >> 7;
    __shared__ float red[4][128];
    __shared__ float s0[128], s1[128], s2[128], lg[10];

    int st = g_start[g], cnt = g_cnt[g];
    int end = st + cnt;
    float p0 = 0.f, p1 = 0.f, p2 = 0.f, p3 = 0.f;
    int r = st + sub;
    for (; r + 12 < end; r += 16) {
        p0 += h[(size_t)(r)      * DD + d];
        p1 += h[(size_t)(r + 4)  * DD + d];
        p2 += h[(size_t)(r + 8)  * DD + d];
        p3 += h[(size_t)(r + 12) * DD + d];
    }
    for (; r < end; r += 4) p0 += h[(size_t)r * DD + d];
    red[sub][d] = (p0 + p1) + (p2 + p3);
    __syncthreads();
    if (sub == 0) s0[d] = (red[0][d] + red[1][d]) + (red[2][d] + red[3][d]);
    __syncthreads();

    if (sub == 0) {
        float acc = fb1[d];
        for (int k = 0; k < 128; k++) acc += s0[k] * fw1[k * 128 + d];
        s1[d] = fmaxf(acc, 0.f);
    }
    __syncthreads();

    if (sub == 0) {
        float acc = fb2[d];
        for (int k = 0; k < 128; k++) acc += s1[k] * fw2[k * 128 + d];
        s2[d] = fmaxf(acc, 0.f);
    }
    __syncthreads();

    if (sub == 0 && d < 10) {
        float a = fb3[d];
        for (int k = 0; k < 128; k++) a += s2[k] * fw3[k * 10 + d];
        lg[d] = a;
    }
    __syncthreads();

    if (threadIdx.x == 0) {
        float m = lg[0];
        for (int c = 1; c < 10; c++) m = fmaxf(m, lg[c]);
        float s = 0.f;
        for (int c = 0; c < 10; c++) s += expf(lg[c] - m);
        float lse = m + logf(s);
        for (int c = 0; c < 10; c++) out[g * 10 + c] = lg[c] - lse;
    }
}

// ---------------------------------------------------------------------------
extern "C" void kernel_launch(void* const* d_in, const int* in_sizes, int n_in,
                              void* d_out, int out_size) {
    const float* x      = (const float*)d_in[0];
    const float* gin_w1 = (const float*)d_in[1];
    const float* gin_b1 = (const float*)d_in[2];
    const float* gin_w2 = (const float*)d_in[3];
    const float* gin_b2 = (const float*)d_in[4];
    const float* gn_w   = (const float*)d_in[5];
    const float* gn_b   = (const float*)d_in[6];
    const float* gn_s   = (const float*)d_in[7];
    const float* fw1    = (const float*)d_in[8];
    const float* fb1    = (const float*)d_in[9];
    const float* fw2    = (const float*)d_in[10];
    const float* fb2    = (const float*)d_in[11];
    const float* fw3    = (const float*)d_in[12];
    const float* fb3    = (const float*)d_in[13];
    const int* ei    = (const int*)d_in[14];   // int32 (JAX x64 disabled)
    const int* batch = (const int*)d_in[15];   // int32
    float* out = (float*)d_out;

    float* bufA;  cudaGetSymbolAddress((void**)&bufA, g_bufA);
    float* bufB;  cudaGetSymbolAddress((void**)&bufB, g_bufB);

    const int gemm_grid = (NN + 63) / 64;
    const int gath_grid = (NN * 32 + 255) / 256;

    // CSR build (once per launch; reused by all 4 layers)
    k_zero<<<(NN + 255) / 256, 256>>>();
    k_hist<<<(NE + 255) / 256, 256>>>(ei, batch);
    k_scan<<<1, 1024>>>();
    k_fill<<<(NE + 255) / 256, 256>>>(ei);

    const float* hin = x;
    for (int l = 0; l < NL; l++) {
        k_gather<<<gath_grid, 256>>>((const float4*)hin, (float4*)bufB);
        k_gemm_relu<<<gemm_grid, 256>>>(bufB, gin_w1 + l * 128 * 128,
                                        gin_b1 + l * 128, bufA, NN);
        k_gemm_relu<<<gemm_grid, 256>>>(bufA, gin_w2 + l * 128 * 128,
                                        gin_b2 + l * 128, bufB, NN);
        k_gnorm<<<NG, 512>>>(bufB, bufA, gn_w + l * 128, gn_b + l * 128,
                             gn_s + l * 128);
        hin = bufA;
    }

    k_head<<<NG, 512>>>(bufA, fw1, fb1, fw2, fb2, fw3, fb3, out);
}

// round 8
// speedup vs baseline: 2.0247x; 1.0234x over previous
#include <cuda_runtime.h>
#include <cuda_bf16.h>
#include <math.h>

#define NN 50000
#define NE 800000
#define NG 128
#define DD 128
#define NL 4

#define SW 136                          // smem row stride (floats): B-frag conflict-free
#define GEMM_SMEM (384 * SW * 4)        // (128+128+64+64) rows * SW * 4B = 208896

__device__ float g_bufA[NN * DD];
__device__ float g_bufB[NN * DD];
__device__ int   g_cnt[NG];
__device__ int   g_start[NG];
__device__ int   g_deg[NN];
__device__ int   g_row[NN + 1];
__device__ int   g_cur[NN];
__device__ int   g_srcs[NE];

// ---------------------------------------------------------------------------
// CSR build
// ---------------------------------------------------------------------------
__global__ void k_zero() {
    int i = blockIdx.x * blockDim.x + threadIdx.x;
    if (i < NN) g_deg[i] = 0;
    if (i < NG) g_cnt[i] = 0;
}

__global__ void k_hist(const int* __restrict__ ei, const int* __restrict__ batch) {
    int i = blockIdx.x * blockDim.x + threadIdx.x;
    if (i < NE) {
        int d = ei[NE + i];
        d = max(0, min(d, NN - 1));
        atomicAdd(&g_deg[d], 1);
    }
    if (i < NN) {
        int g = batch[i];
        g = max(0, min(g, NG - 1));
        atomicAdd(&g_cnt[g], 1);
    }
}

__global__ __launch_bounds__(1024) void k_scan() {
    const int T = 1024;
    const int PER = (NN + T - 1) / T;
    __shared__ int ssum[T];
    int t = threadIdx.x;
    int lo = t * PER, hi = min(lo + PER, NN);

    int s = 0;
    for (int i = lo; i < hi; i++) s += g_deg[i];
    ssum[t] = s;
    __syncthreads();
    for (int off = 1; off < T; off <<= 1) {
        int v = (t >= off) ? ssum[t - off] : 0;
        __syncthreads();
        ssum[t] += v;
        __syncthreads();
    }
    int run = ssum[t] - s;
    for (int i = lo; i < hi; i++) {
        g_row[i] = run;
        g_cur[i] = run;
        run += g_deg[i];
    }
    if (t == T - 1) g_row[NN] = ssum[T - 1];
    if (t == 0) {
        int acc = 0;
        for (int g = 0; g < NG; g++) { g_start[g] = acc; acc += g_cnt[g]; }
    }
}

__global__ void k_fill(const int* __restrict__ ei) {
    int i = blockIdx.x * blockDim.x + threadIdx.x;
    if (i >= NE) return;
    int s = ei[i];
    int d = ei[NE + i];
    s = max(0, min(s, NN - 1));
    d = max(0, min(d, NN - 1));
    int slot = atomicAdd(&g_cur[d], 1);
    g_srcs[slot] = s;
}

// ---------------------------------------------------------------------------
// CSR gather: out[n] = h[n] + sum_{src in csr[n]} h[src]
// ---------------------------------------------------------------------------
__global__ __launch_bounds__(256) void k_gather(const float4* __restrict__ h,
                                                float4* __restrict__ out) {
    int n = (blockIdx.x * blockDim.x + threadIdx.x) >> 5;
    if (n >= NN) return;
    int lane = threadIdx.x & 31;

    float4 a0 = h[n * 32 + lane];
    float4 a1 = make_float4(0.f, 0.f, 0.f, 0.f);
    float4 a2 = a1, a3 = a1;

    int e = g_row[n], end = g_row[n + 1];
    for (; e + 3 < end; e += 4) {
        int s0 = g_srcs[e], s1 = g_srcs[e + 1], s2 = g_srcs[e + 2], s3 = g_srcs[e + 3];
        float4 v0 = h[s0 * 32 + lane];
        float4 v1 = h[s1 * 32 + lane];
        float4 v2 = h[s2 * 32 + lane];
        float4 v3 = h[s3 * 32 + lane];
        a0.x += v0.x; a0.y += v0.y; a0.z += v0.z; a0.w += v0.w;
        a1.x += v1.x; a1.y += v1.y; a1.z += v1.z; a1.w += v1.w;
        a2.x += v2.x; a2.y += v2.y; a2.z += v2.z; a2.w += v2.w;
        a3.x += v3.x; a3.y += v3.y; a3.z += v3.z; a3.w += v3.w;
    }
    for (; e < end; e++) {
        int s0 = g_srcs[e];
        float4 v0 = h[s0 * 32 + lane];
        a0.x += v0.x; a0.y += v0.y; a0.z += v0.z; a0.w += v0.w;
    }
    float4 r;
    r.x = (a0.x + a1.x) + (a2.x + a3.x);
    r.y = (a0.y + a1.y) + (a2.y + a3.y);
    r.z = (a0.z + a1.z) + (a2.z + a3.z);
    r.w = (a0.w + a1.w) + (a2.w + a3.w);
    out[n * 32 + lane] = r;
}

// ---------------------------------------------------------------------------
// Tensor-core GEMM (3xTF32 split, fp32-class accuracy) + bias + ReLU.
// Persistent blocks: W hi/lo staged to smem once; 64-row A tiles streamed.
// 8 warps: warp w -> rows (w/2)*16..+15, cols (w&1)*64..+63 of the tile.
// mma.sync.m16n8k8: D += Ahi*Bhi + Ahi*Blo + Alo*Bhi.
// ---------------------------------------------------------------------------
__device__ __forceinline__ unsigned f2tf(float x) {
    unsigned r;
    asm("cvt.rna.tf32.f32 %0, %1;" : "=r"(r) : "f"(x));
    return r;
}

__device__ __forceinline__ void mma8(float* d, unsigned a0, unsigned a1,
                                     unsigned a2, unsigned a3,
                                     unsigned b0, unsigned b1) {
    asm volatile(
        "mma.sync.aligned.m16n8k8.row.col.f32.tf32.tf32.f32 "
        "{%0,%1,%2,%3}, {%4,%5,%6,%7}, {%8,%9}, {%0,%1,%2,%3};"
        : "+f"(d[0]), "+f"(d[1]), "+f"(d[2]), "+f"(d[3])
        : "r"(a0), "r"(a1), "r"(a2), "r"(a3), "r"(b0), "r"(b1));
}

__global__ __launch_bounds__(256) void k_gemm_tc(const float* __restrict__ A,
                                                 const float* __restrict__ W,
                                                 const float* __restrict__ bias,
                                                 float* __restrict__ out, int M) {
    extern __shared__ float dyn[];
    float* sWhi = dyn;                  // [128][SW]
    float* sWlo = sWhi + 128 * SW;
    float* sAhi = sWlo + 128 * SW;      // [64][SW]
    float* sAlo = sAhi + 64 * SW;

    int tid = threadIdx.x;

    // Stage W hi/lo once per block
    for (int idx = tid; idx < 128 * 128; idx += 256) {
        int k = idx >> 7, n = idx & 127;
        float v = W[idx];
        float hi = __uint_as_float(f2tf(v));
        sWhi[k * SW + n] = hi;
        sWlo[k * SW + n] = __uint_as_float(f2tf(v - hi));
    }
    __syncthreads();

    int lane = tid & 31;
    int w = tid >> 5;
    int rw = (w >> 1) * 16;             // warp row offset in tile
    int nb = (w & 1) * 64;              // warp col offset
    int quad = lane >> 2, tq = lane & 3;

    int ntiles = (M + 63) / 64;
    for (int t = blockIdx.x; t < ntiles; t += gridDim.x) {
        int row0 = t * 64;

        // Stage A tile hi/lo
        for (int idx = tid; idx < 64 * 128; idx += 256) {
            int r = idx >> 7, c = idx & 127;
            float v = (row0 + r < M) ? A[(size_t)(row0 + r) * DD + c] : 0.f;
            float hi = __uint_as_float(f2tf(v));
            sAhi[r * SW + c] = hi;
            sAlo[r * SW + c] = __uint_as_float(f2tf(v - hi));
        }
        __syncthreads();

        float acc[8][4];
#pragma unroll
        for (int i = 0; i < 8; i++)
#pragma unroll
            for (int j = 0; j < 4; j++) acc[i][j] = 0.f;

#pragma unroll
        for (int kk = 0; kk < 16; kk++) {
            int k0 = kk * 8;
            const float* pAh = sAhi + (rw + quad) * SW + k0 + tq;
            const float* pAl = sAlo + (rw + quad) * SW + k0 + tq;
            unsigned ah0 = __float_as_uint(pAh[0]);
            unsigned ah1 = __float_as_uint(pAh[8 * SW]);
            unsigned ah2 = __float_as_uint(pAh[4]);
            unsigned ah3 = __float_as_uint(pAh[8 * SW + 4]);
            unsigned al0 = __float_as_uint(pAl[0]);
            unsigned al1 = __float_as_uint(pAl[8 * SW]);
            unsigned al2 = __float_as_uint(pAl[4]);
            unsigned al3 = __float_as_uint(pAl[8 * SW + 4]);

#pragma unroll
            for (int nt = 0; nt < 8; nt++) {
                int n0 = nb + nt * 8;
                const float* pBh = sWhi + (k0 + tq) * SW + n0 + quad;
                const float* pBl = sWlo + (k0 + tq) * SW + n0 + quad;
                unsigned bh0 = __float_as_uint(pBh[0]);
                unsigned bh1 = __float_as_uint(pBh[4 * SW]);
                unsigned bl0 = __float_as_uint(pBl[0]);
                unsigned bl1 = __float_as_uint(pBl[4 * SW]);
                mma8(acc[nt], ah0, ah1, ah2, ah3, bh0, bh1);
                mma8(acc[nt], ah0, ah1, ah2, ah3, bl0, bl1);
                mma8(acc[nt], al0, al1, al2, al3, bh0, bh1);
            }
        }

        // Epilogue: bias + relu, float2 stores
        int gr0 = row0 + rw + quad;
        int gr1 = gr0 + 8;
#pragma unroll
        for (int nt = 0; nt < 8; nt++) {
            int c0 = nb + nt * 8 + (tq << 1);
            float bx = bias[c0], by = bias[c0 + 1];
            if (gr0 < M) {
                float2 o;
                o.x = fmaxf(acc[nt][0] + bx, 0.f);
                o.y = fmaxf(acc[nt][1] + by, 0.f);
                *(float2*)(out + (size_t)gr0 * DD + c0) = o;
            }
            if (gr1 < M) {
                float2 o;
                o.x = fmaxf(acc[nt][2] + bx, 0.f);
                o.y = fmaxf(acc[nt][3] + by, 0.f);
                *(float2*)(out + (size_t)gr1 * DD + c0) = o;
            }
        }
        __syncthreads();
    }
}

// ---------------------------------------------------------------------------
// GraphNorm + ReLU, fused mean/var, 8-way unroll. 512 threads.
// ---------------------------------------------------------------------------
__global__ __launch_bounds__(512) void k_gnorm(const float* __restrict__ in,
                                               float* __restrict__ out,
                                               const float* __restrict__ w,
                                               const float* __restrict__ b,
                                               const float* __restrict__ ms) {
    __shared__ float redA[4][128];
    __shared__ float redB[4][128];
    int g = blockIdx.x;
    int d = threadIdx.x & 127;
    int sub = threadIdx.x >> 7;
    int st = g_start[g], cnt = g_cnt[g];
    if (cnt == 0) return;
    int end = st + cnt;

    float s1 = 0.f, s2 = 0.f;
    int r = st + sub;
    for (; r + 28 < end; r += 32) {
        float v0 = in[(size_t)(r)      * DD + d];
        float v1 = in[(size_t)(r + 4)  * DD + d];
        float v2 = in[(size_t)(r + 8)  * DD + d];
        float v3 = in[(size_t)(r + 12) * DD + d];
        float v4 = in[(size_t)(r + 16) * DD + d];
        float v5 = in[(size_t)(r + 20) * DD + d];
        float v6 = in[(size_t)(r + 24) * DD + d];
        float v7 = in[(size_t)(r + 28) * DD + d];
        s1 += ((v0 + v1) + (v2 + v3)) + ((v4 + v5) + (v6 + v7));
        s2 += ((v0 * v0 + v1 * v1) + (v2 * v2 + v3 * v3)) +
              ((v4 * v4 + v5 * v5) + (v6 * v6 + v7 * v7));
    }
    for (; r < end; r += 4) {
        float v = in[(size_t)r * DD + d];
        s1 += v;
        s2 += v * v;
    }
    redA[sub][d] = s1;
    redB[sub][d] = s2;
    __syncthreads();
    float S1 = (redA[0][d] + redA[1][d]) + (redA[2][d] + redA[3][d]);
    float S2 = (redB[0][d] + redB[1][d]) + (redB[2][d] + redB[3][d]);

    float inv_n = 1.0f / (float)cnt;
    float mh = S1 * inv_n;
    float m  = mh * ms[d];
    float var = S2 * inv_n - 2.f * m * mh + m * m;
    float sc = w[d] * rsqrtf(var + 1e-5f);
    float bd = b[d];

#pragma unroll 8
    for (r = st + sub; r < end; r += 4) {
        float v = in[(size_t)r * DD + d];
        out[(size_t)r * DD + d] = fmaxf((v - m) * sc + bd, 0.f);
    }
}

// ---------------------------------------------------------------------------
// Head: sum-pool per graph + MLP + log_softmax
// ---------------------------------------------------------------------------
__global__ __launch_bounds__(512) void k_head(const float* __restrict__ h,
                                              const float* __restrict__ fw1,
                                              const float* __restrict__ fb1,
                                              const float* __restrict__ fw2,
                                              const float* __restrict__ fb2,
                                              const float* __restrict__ fw3,
                                              const float* __restrict__ fb3,
                                              float* __restrict__ out) {
    int g = blockIdx.x;
    int d = threadIdx.x & 127;
    int sub = threadIdx.x >> 7;
    __shared__ float red[4][128];
    __shared__ float s0[128], s1[128], s2[128], lg[10];

    int st = g_start[g], cnt = g_cnt[g];
    int end = st + cnt;
    float p0 = 0.f, p1 = 0.f, p2 = 0.f, p3 = 0.f;
    int r = st + sub;
    for (; r + 12 < end; r += 16) {
        p0 += h[(size_t)(r)      * DD + d];
        p1 += h[(size_t)(r + 4)  * DD + d];
        p2 += h[(size_t)(r + 8)  * DD + d];
        p3 += h[(size_t)(r + 12) * DD + d];
    }
    for (; r < end; r += 4) p0 += h[(size_t)r * DD + d];
    red[sub][d] = (p0 + p1) + (p2 + p3);
    __syncthreads();
    if (sub == 0) s0[d] = (red[0][d] + red[1][d]) + (red[2][d] + red[3][d]);
    __syncthreads();

    if (sub == 0) {
        float acc = fb1[d];
        for (int k = 0; k < 128; k++) acc += s0[k] * fw1[k * 128 + d];
        s1[d] = fmaxf(acc, 0.f);
    }
    __syncthreads();

    if (sub == 0) {
        float acc = fb2[d];
        for (int k = 0; k < 128; k++) acc += s1[k] * fw2[k * 128 + d];
        s2[d] = fmaxf(acc, 0.f);
    }
    __syncthreads();

    if (sub == 0 && d < 10) {
        float a = fb3[d];
        for (int k = 0; k < 128; k++) a += s2[k] * fw3[k * 10 + d];
        lg[d] = a;
    }
    __syncthreads();

    if (threadIdx.x == 0) {
        float m = lg[0];
        for (int c = 1; c < 10; c++) m = fmaxf(m, lg[c]);
        float s = 0.f;
        for (int c = 0; c < 10; c++) s += expf(lg[c] - m);
        float lse = m + logf(s);
        for (int c = 0; c < 10; c++) out[g * 10 + c] = lg[c] - lse;
    }
}

// ---------------------------------------------------------------------------
extern "C" void kernel_launch(void* const* d_in, const int* in_sizes, int n_in,
                              void* d_out, int out_size) {
    const float* x      = (const float*)d_in[0];
    const float* gin_w1 = (const float*)d_in[1];
    const float* gin_b1 = (const float*)d_in[2];
    const float* gin_w2 = (const float*)d_in[3];
    const float* gin_b2 = (const float*)d_in[4];
    const float* gn_w   = (const float*)d_in[5];
    const float* gn_b   = (const float*)d_in[6];
    const float* gn_s   = (const float*)d_in[7];
    const float* fw1    = (const float*)d_in[8];
    const float* fb1    = (const float*)d_in[9];
    const float* fw2    = (const float*)d_in[10];
    const float* fb2    = (const float*)d_in[11];
    const float* fw3    = (const float*)d_in[12];
    const float* fb3    = (const float*)d_in[13];
    const int* ei    = (const int*)d_in[14];
    const int* batch = (const int*)d_in[15];
    float* out = (float*)d_out;

    float* bufA;  cudaGetSymbolAddress((void**)&bufA, g_bufA);
    float* bufB;  cudaGetSymbolAddress((void**)&bufB, g_bufB);

    cudaFuncSetAttribute(k_gemm_tc, cudaFuncAttributeMaxDynamicSharedMemorySize,
                         GEMM_SMEM);

    const int gath_grid = (NN * 32 + 255) / 256;

    // CSR build (once per launch)
    k_zero<<<(NN + 255) / 256, 256>>>();
    k_hist<<<(NE + 255) / 256, 256>>>(ei, batch);
    k_scan<<<1, 1024>>>();
    k_fill<<<(NE + 255) / 256, 256>>>(ei);

    const float* hin = x;
    for (int l = 0; l < NL; l++) {
        k_gather<<<gath_grid, 256>>>((const float4*)hin, (float4*)bufB);
        k_gemm_tc<<<148, 256, GEMM_SMEM>>>(bufB, gin_w1 + l * 128 * 128,
                                           gin_b1 + l * 128, bufA, NN);
        k_gemm_tc<<<148, 256, GEMM_SMEM>>>(bufA, gin_w2 + l * 128 * 128,
                                           gin_b2 + l * 128, bufB, NN);
        k_gnorm<<<NG, 512>>>(bufB, bufA, gn_w + l * 128, gn_b + l * 128,
                             gn_s + l * 128);
        hin = bufA;
    }

    k_head<<<NG, 512>>>(bufA, fw1, fb1, fw2, fb2, fw3, fb3, out);
}

// round 13
// speedup vs baseline: 2.6014x; 1.2848x over previous
#include <cuda_runtime.h>
#include <cuda_bf16.h>
#include <math.h>

#define NN 50000
#define NE 800000
#define NG 128
#define DD 128
#define NL 4

#define SA 68                            // smem pair-stride (b32 units); 68%32=4 -> conflict-free frags
#define GEMM_SMEM (384 * SA * 4)         // (128+128+64+64) rows of 64 pairs, stride 68 = 104448 B

__device__ float g_bufA[NN * DD];
__device__ float g_bufB[NN * DD];
__device__ int   g_cnt[NG];
__device__ int   g_start[NG];
__device__ int   g_deg[NN];
__device__ int   g_row[NN + 1];
__device__ int   g_cur[NN];
__device__ int   g_srcs[NE];

// ---------------------------------------------------------------------------
// CSR build
// ---------------------------------------------------------------------------
__global__ void k_zero() {
    int i = blockIdx.x * blockDim.x + threadIdx.x;
    if (i < NN) g_deg[i] = 0;
    if (i < NG) g_cnt[i] = 0;
}

__global__ void k_hist(const int* __restrict__ ei, const int* __restrict__ batch) {
    int i = blockIdx.x * blockDim.x + threadIdx.x;
    if (i < NE) {
        int d = ei[NE + i];
        d = max(0, min(d, NN - 1));
        atomicAdd(&g_deg[d], 1);
    }
    if (i < NN) {
        int g = batch[i];
        g = max(0, min(g, NG - 1));
        atomicAdd(&g_cnt[g], 1);
    }
}

__global__ __launch_bounds__(1024) void k_scan() {
    const int T = 1024;
    const int PER = (NN + T - 1) / T;
    __shared__ int ssum[T];
    int t = threadIdx.x;
    int lo = t * PER, hi = min(lo + PER, NN);

    int s = 0;
    for (int i = lo; i < hi; i++) s += g_deg[i];
    ssum[t] = s;
    __syncthreads();
    for (int off = 1; off < T; off <<= 1) {
        int v = (t >= off) ? ssum[t - off] : 0;
        __syncthreads();
        ssum[t] += v;
        __syncthreads();
    }
    int run = ssum[t] - s;
    for (int i = lo; i < hi; i++) {
        g_row[i] = run;
        g_cur[i] = run;
        run += g_deg[i];
    }
    if (t == T - 1) g_row[NN] = ssum[T - 1];
    if (t == 0) {
        int acc = 0;
        for (int g = 0; g < NG; g++) { g_start[g] = acc; acc += g_cnt[g]; }
    }
}

__global__ void k_fill(const int* __restrict__ ei) {
    int i = blockIdx.x * blockDim.x + threadIdx.x;
    if (i >= NE) return;
    int s = ei[i];
    int d = ei[NE + i];
    s = max(0, min(s, NN - 1));
    d = max(0, min(d, NN - 1));
    int slot = atomicAdd(&g_cur[d], 1);
    g_srcs[slot] = s;
}

// ---------------------------------------------------------------------------
// CSR gather: out[n] = h[n] + sum_{src in csr[n]} h[src]
// ---------------------------------------------------------------------------
__global__ __launch_bounds__(256) void k_gather(const float4* __restrict__ h,
                                                float4* __restrict__ out) {
    int n = (blockIdx.x * blockDim.x + threadIdx.x) >> 5;
    if (n >= NN) return;
    int lane = threadIdx.x & 31;

    float4 a0 = h[n * 32 + lane];
    float4 a1 = make_float4(0.f, 0.f, 0.f, 0.f);
    float4 a2 = a1, a3 = a1;

    int e = g_row[n], end = g_row[n + 1];
    for (; e + 3 < end; e += 4) {
        int s0 = g_srcs[e], s1 = g_srcs[e + 1], s2 = g_srcs[e + 2], s3 = g_srcs[e + 3];
        float4 v0 = h[s0 * 32 + lane];
        float4 v1 = h[s1 * 32 + lane];
        float4 v2 = h[s2 * 32 + lane];
        float4 v3 = h[s3 * 32 + lane];
        a0.x += v0.x; a0.y += v0.y; a0.z += v0.z; a0.w += v0.w;
        a1.x += v1.x; a1.y += v1.y; a1.z += v1.z; a1.w += v1.w;
        a2.x += v2.x; a2.y += v2.y; a2.z += v2.z; a2.w += v2.w;
        a3.x += v3.x; a3.y += v3.y; a3.z += v3.z; a3.w += v3.w;
    }
    for (; e < end; e++) {
        int s0 = g_srcs[e];
        float4 v0 = h[s0 * 32 + lane];
        a0.x += v0.x; a0.y += v0.y; a0.z += v0.z; a0.w += v0.w;
    }
    float4 r;
    r.x = (a0.x + a1.x) + (a2.x + a3.x);
    r.y = (a0.y + a1.y) + (a2.y + a3.y);
    r.z = (a0.z + a1.z) + (a2.z + a3.z);
    r.w = (a0.w + a1.w) + (a2.w + a3.w);
    out[n * 32 + lane] = r;
}

// ---------------------------------------------------------------------------
// Tensor-core GEMM via 3xBF16 split (m16n8k16): D += Ahi*Bhi + Ahi*Blo + Alo*Bhi.
// hi = bf16(v), lo = bf16(v - hi) -> 16 effective mantissa bits, err ~4e-6/product.
// Persistent blocks; W hi/lo staged once; 64-row A tiles streamed.
// Pairs (2 bf16 per b32) stored k-pairwise; stride SA=68 -> conflict-free LDS.
// ---------------------------------------------------------------------------
__device__ __forceinline__ void split_pack(float x, float y,
                                           unsigned& hi, unsigned& lo) {
    __nv_bfloat16 hx = __float2bfloat16(x);
    __nv_bfloat16 hy = __float2bfloat16(y);
    __nv_bfloat16 lx = __float2bfloat16(x - __bfloat162float(hx));
    __nv_bfloat16 ly = __float2bfloat16(y - __bfloat162float(hy));
    hi = ((unsigned)__bfloat16_as_ushort(hy) << 16) | __bfloat16_as_ushort(hx);
    lo = ((unsigned)__bfloat16_as_ushort(ly) << 16) | __bfloat16_as_ushort(lx);
}

__device__ __forceinline__ void mma16(float* d, unsigned a0, unsigned a1,
                                      unsigned a2, unsigned a3,
                                      unsigned b0, unsigned b1) {
    asm volatile(
        "mma.sync.aligned.m16n8k16.row.col.f32.bf16.bf16.f32 "
        "{%0,%1,%2,%3}, {%4,%5,%6,%7}, {%8,%9}, {%0,%1,%2,%3};"
        : "+f"(d[0]), "+f"(d[1]), "+f"(d[2]), "+f"(d[3])
        : "r"(a0), "r"(a1), "r"(a2), "r"(a3), "r"(b0), "r"(b1));
}

__global__ __launch_bounds__(256) void k_gemm_bf3(const float* __restrict__ A,
                                                  const float* __restrict__ W,
                                                  const float* __restrict__ bias,
                                                  float* __restrict__ out, int M) {
    extern __shared__ unsigned dyn[];
    unsigned* sWhi = dyn;                // [128 n][64 kp] stride SA
    unsigned* sWlo = sWhi + 128 * SA;
    unsigned* sAhi = sWlo + 128 * SA;    // [64 r][64 kp] stride SA
    unsigned* sAlo = sAhi + 64 * SA;

    int tid = threadIdx.x;

    // Stage W hi/lo once: pair {W[2kp][n], W[2kp+1][n]} at sW[n*SA+kp]
    for (int idx = tid; idx < 64 * 128; idx += 256) {
        int kp = idx >> 7, n = idx & 127;        // consecutive tid -> consecutive n (coalesced)
        float v0 = W[(2 * kp) * 128 + n];
        float v1 = W[(2 * kp + 1) * 128 + n];
        unsigned hi, lo;
        split_pack(v0, v1, hi, lo);
        sWhi[n * SA + kp] = hi;
        sWlo[n * SA + kp] = lo;
    }
    __syncthreads();

    int lane = tid & 31;
    int w = tid >> 5;
    int rw = (w >> 1) * 16;             // warp row offset in tile
    int nb = (w & 1) * 64;              // warp col offset
    int quad = lane >> 2, tq = lane & 3;

    int ntiles = (M + 63) / 64;
    for (int t = blockIdx.x; t < ntiles; t += gridDim.x) {
        int row0 = t * 64;

        // Stage A tile: pair {A[r][2kp], A[r][2kp+1]} at sA[r*SA+kp]
        const float2* A2 = (const float2*)A;
        for (int idx = tid; idx < 64 * 64; idx += 256) {
            int r = idx >> 6, kp = idx & 63;     // consecutive tid -> consecutive kp (coalesced LDG.64)
            float2 v = make_float2(0.f, 0.f);
            if (row0 + r < M) v = A2[(size_t)(row0 + r) * 64 + kp];
            unsigned hi, lo;
            split_pack(v.x, v.y, hi, lo);
            sAhi[r * SA + kp] = hi;
            sAlo[r * SA + kp] = lo;
        }
        __syncthreads();

        float acc[8][4];
#pragma unroll
        for (int i = 0; i < 8; i++)
#pragma unroll
            for (int j = 0; j < 4; j++) acc[i][j] = 0.f;

#pragma unroll
        for (int kk = 0; kk < 8; kk++) {         // 8 k16 steps, kp0 = kk*8
            int kp0 = kk * 8;
            const unsigned* pAh = sAhi + (rw + quad) * SA + kp0 + tq;
            const unsigned* pAl = sAlo + (rw + quad) * SA + kp0 + tq;
            unsigned ah0 = pAh[0];
            unsigned ah1 = pAh[8 * SA];
            unsigned ah2 = pAh[4];
            unsigned ah3 = pAh[8 * SA + 4];
            unsigned al0 = pAl[0];
            unsigned al1 = pAl[8 * SA];
            unsigned al2 = pAl[4];
            unsigned al3 = pAl[8 * SA + 4];

#pragma unroll
            for (int nt = 0; nt < 8; nt++) {
                int n0 = nb + nt * 8;
                const unsigned* pBh = sWhi + (n0 + quad) * SA + kp0 + tq;
                const unsigned* pBl = sWlo + (n0 + quad) * SA + kp0 + tq;
                unsigned bh0 = pBh[0];
                unsigned bh1 = pBh[4];
                unsigned bl0 = pBl[0];
                unsigned bl1 = pBl[4];
                mma16(acc[nt], ah0, ah1, ah2, ah3, bh0, bh1);
                mma16(acc[nt], ah0, ah1, ah2, ah3, bl0, bl1);
                mma16(acc[nt], al0, al1, al2, al3, bh0, bh1);
            }
        }

        // Epilogue: bias + relu, float2 stores
        int gr0 = row0 + rw + quad;
        int gr1 = gr0 + 8;
#pragma unroll
        for (int nt = 0; nt < 8; nt++) {
            int c0 = nb + nt * 8 + (tq << 1);
            float bx = bias[c0], by = bias[c0 + 1];
            if (gr0 < M) {
                float2 o;
                o.x = fmaxf(acc[nt][0] + bx, 0.f);
                o.y = fmaxf(acc[nt][1] + by, 0.f);
                *(float2*)(out + (size_t)gr0 * DD + c0) = o;
            }
            if (gr1 < M) {
                float2 o;
                o.x = fmaxf(acc[nt][2] + bx, 0.f);
                o.y = fmaxf(acc[nt][3] + by, 0.f);
                *(float2*)(out + (size_t)gr1 * DD + c0) = o;
            }
        }
        __syncthreads();
    }
}

// ---------------------------------------------------------------------------
// GraphNorm + ReLU, fused mean/var, 8-way unroll. 512 threads.
// ---------------------------------------------------------------------------
__global__ __launch_bounds__(512) void k_gnorm(const float* __restrict__ in,
                                               float* __restrict__ out,
                                               const float* __restrict__ w,
                                               const float* __restrict__ b,
                                               const float* __restrict__ ms) {
    __shared__ float redA[4][128];
    __shared__ float redB[4][128];
    int g = blockIdx.x;
    int d = threadIdx.x & 127;
    int sub = threadIdx.x >> 7;
    int st = g_start[g], cnt = g_cnt[g];
    if (cnt == 0) return;
    int end = st + cnt;

    float s1 = 0.f, s2 = 0.f;
    int r = st + sub;
    for (; r + 28 < end; r += 32) {
        float v0 = in[(size_t)(r)      * DD + d];
        float v1 = in[(size_t)(r + 4)  * DD + d];
        float v2 = in[(size_t)(r + 8)  * DD + d];
        float v3 = in[(size_t)(r + 12) * DD + d];
        float v4 = in[(size_t)(r + 16) * DD + d];
        float v5 = in[(size_t)(r + 20) * DD + d];
        float v6 = in[(size_t)(r + 24) * DD + d];
        float v7 = in[(size_t)(r + 28) * DD + d];
        s1 += ((v0 + v1) + (v2 + v3)) + ((v4 + v5) + (v6 + v7));
        s2 += ((v0 * v0 + v1 * v1) + (v2 * v2 + v3 * v3)) +
              ((v4 * v4 + v5 * v5) + (v6 * v6 + v7 * v7));
    }
    for (; r < end; r += 4) {
        float v = in[(size_t)r * DD + d];
        s1 += v;
        s2 += v * v;
    }
    redA[sub][d] = s1;
    redB[sub][d] = s2;
    __syncthreads();
    float S1 = (redA[0][d] + redA[1][d]) + (redA[2][d] + redA[3][d]);
    float S2 = (redB[0][d] + redB[1][d]) + (redB[2][d] + redB[3][d]);

    float inv_n = 1.0f / (float)cnt;
    float mh = S1 * inv_n;
    float m  = mh * ms[d];
    float var = S2 * inv_n - 2.f * m * mh + m * m;
    float sc = w[d] * rsqrtf(var + 1e-5f);
    float bd = b[d];

#pragma unroll 8
    for (r = st + sub; r < end; r += 4) {
        float v = in[(size_t)r * DD + d];
        out[(size_t)r * DD + d] = fmaxf((v - m) * sc + bd, 0.f);
    }
}

// ---------------------------------------------------------------------------
// Head: sum-pool per graph + MLP + log_softmax
// ---------------------------------------------------------------------------
__global__ __launch_bounds__(512) void k_head(const float* __restrict__ h,
                                              const float* __restrict__ fw1,
                                              const float* __restrict__ fb1,
                                              const float* __restrict__ fw2,
                                              const float* __restrict__ fb2,
                                              const float* __restrict__ fw3,
                                              const float* __restrict__ fb3,
                                              float* __restrict__ out) {
    int g = blockIdx.x;
    int d = threadIdx.x & 127;
    int sub = threadIdx.x >> 7;
    __shared__ float red[4][128];
    __shared__ float s0[128], s1[128], s2[128], lg[10];

    int st = g_start[g], cnt = g_cnt[g];
    int end = st + cnt;
    float p0 = 0.f, p1 = 0.f, p2 = 0.f, p3 = 0.f;
    int r = st + sub;
    for (; r + 12 < end; r += 16) {
        p0 += h[(size_t)(r)      * DD + d];
        p1 += h[(size_t)(r + 4)  * DD + d];
        p2 += h[(size_t)(r + 8)  * DD + d];
        p3 += h[(size_t)(r + 12) * DD + d];
    }
    for (; r < end; r += 4) p0 += h[(size_t)r * DD + d];
    red[sub][d] = (p0 + p1) + (p2 + p3);
    __syncthreads();
    if (sub == 0) s0[d] = (red[0][d] + red[1][d]) + (red[2][d] + red[3][d]);
    __syncthreads();

    if (sub == 0) {
        float acc = fb1[d];
        for (int k = 0; k < 128; k++) acc += s0[k] * fw1[k * 128 + d];
        s1[d] = fmaxf(acc, 0.f);
    }
    __syncthreads();

    if (sub == 0) {
        float acc = fb2[d];
        for (int k = 0; k < 128; k++) acc += s1[k] * fw2[k * 128 + d];
        s2[d] = fmaxf(acc, 0.f);
    }
    __syncthreads();

    if (sub == 0 && d < 10) {
        float a = fb3[d];
        for (int k = 0; k < 128; k++) a += s2[k] * fw3[k * 10 + d];
        lg[d] = a;
    }
    __syncthreads();

    if (threadIdx.x == 0) {
        float m = lg[0];
        for (int c = 1; c < 10; c++) m = fmaxf(m, lg[c]);
        float s = 0.f;
        for (int c = 0; c < 10; c++) s += expf(lg[c] - m);
        float lse = m + logf(s);
        for (int c = 0; c < 10; c++) out[g * 10 + c] = lg[c] - lse;
    }
}

// ---------------------------------------------------------------------------
extern "C" void kernel_launch(void* const* d_in, const int* in_sizes, int n_in,
                              void* d_out, int out_size) {
    const float* x      = (const float*)d_in[0];
    const float* gin_w1 = (const float*)d_in[1];
    const float* gin_b1 = (const float*)d_in[2];
    const float* gin_w2 = (const float*)d_in[3];
    const float* gin_b2 = (const float*)d_in[4];
    const float* gn_w   = (const float*)d_in[5];
    const float* gn_b   = (const float*)d_in[6];
    const float* gn_s   = (const float*)d_in[7];
    const float* fw1    = (const float*)d_in[8];
    const float* fb1    = (const float*)d_in[9];
    const float* fw2    = (const float*)d_in[10];
    const float* fb2    = (const float*)d_in[11];
    const float* fw3    = (const float*)d_in[12];
    const float* fb3    = (const float*)d_in[13];
    const int* ei    = (const int*)d_in[14];
    const int* batch = (const int*)d_in[15];
    float* out = (float*)d_out;

    float* bufA;  cudaGetSymbolAddress((void**)&bufA, g_bufA);
    float* bufB;  cudaGetSymbolAddress((void**)&bufB, g_bufB);

    cudaFuncSetAttribute(k_gemm_bf3, cudaFuncAttributeMaxDynamicSharedMemorySize,
                         GEMM_SMEM);

    const int gath_grid = (NN * 32 + 255) / 256;

    // CSR build (once per launch)
    k_zero<<<(NN + 255) / 256, 256>>>();
    k_hist<<<(NE + 255) / 256, 256>>>(ei, batch);
    k_scan<<<1, 1024>>>();
    k_fill<<<(NE + 255) / 256, 256>>>(ei);

    const float* hin = x;
    for (int l = 0; l < NL; l++) {
        k_gather<<<gath_grid, 256>>>((const float4*)hin, (float4*)bufB);
        k_gemm_bf3<<<148, 256, GEMM_SMEM>>>(bufB, gin_w1 + l * 128 * 128,
                                            gin_b1 + l * 128, bufA, NN);
        k_gemm_bf3<<<148, 256, GEMM_SMEM>>>(bufA, gin_w2 + l * 128 * 128,
                                            gin_b2 + l * 128, bufB, NN);
        k_gnorm<<<NG, 512>>>(bufB, bufA, gn_w + l * 128, gn_b + l * 128,
                             gn_s + l * 128);
        hin = bufA;
    }

    k_head<<<NG, 512>>>(bufA, fw1, fb1, fw2, fb2, fw3, fb3, out);
}

// round 16
// speedup vs baseline: 2.8825x; 1.1081x over previous
#include <cuda_runtime.h>
#include <cuda_bf16.h>
#include <math.h>

#define NN 50000
#define NE 800000
#define NG 128
#define DD 128
#define NL 4

#define SA 68                            // smem pair-stride (b32); 68%32=4 -> conflict-free frags
#define GEMM_SMEM (640 * SA * 4)         // W1(2*128) + W2(2*128) + A(2*64) rows = 174080 B

__device__ float g_bufA[NN * DD];
__device__ float g_bufB[NN * DD];
__device__ int   g_cnt[NG];
__device__ int   g_start[NG];
__device__ int   g_deg[NN];
__device__ int   g_row[NN + 1];
__device__ int   g_cur[NN];
__device__ int   g_srcs[NE];

// ---------------------------------------------------------------------------
// CSR build
// ---------------------------------------------------------------------------
__global__ void k_zero() {
    int i = blockIdx.x * blockDim.x + threadIdx.x;
    if (i < NN) g_deg[i] = 0;
    if (i < NG) g_cnt[i] = 0;
}

__global__ void k_hist(const int* __restrict__ ei, const int* __restrict__ batch) {
    int i = blockIdx.x * blockDim.x + threadIdx.x;
    if (i < NE) {
        int d = ei[NE + i];
        d = max(0, min(d, NN - 1));
        atomicAdd(&g_deg[d], 1);
    }
    if (i < NN) {
        int g = batch[i];
        g = max(0, min(g, NG - 1));
        atomicAdd(&g_cnt[g], 1);
    }
}

__global__ __launch_bounds__(1024) void k_scan() {
    const int T = 1024;
    const int PER = (NN + T - 1) / T;
    __shared__ int ssum[T];
    int t = threadIdx.x;
    int lo = t * PER, hi = min(lo + PER, NN);

    int s = 0;
    for (int i = lo; i < hi; i++) s += g_deg[i];
    ssum[t] = s;
    __syncthreads();
    for (int off = 1; off < T; off <<= 1) {
        int v = (t >= off) ? ssum[t - off] : 0;
        __syncthreads();
        ssum[t] += v;
        __syncthreads();
    }
    int run = ssum[t] - s;
    for (int i = lo; i < hi; i++) {
        g_row[i] = run;
        g_cur[i] = run;
        run += g_deg[i];
    }
    if (t == T - 1) g_row[NN] = ssum[T - 1];
    if (t == 0) {
        int acc = 0;
        for (int g = 0; g < NG; g++) { g_start[g] = acc; acc += g_cnt[g]; }
    }
}

__global__ void k_fill(const int* __restrict__ ei) {
    int i = blockIdx.x * blockDim.x + threadIdx.x;
    if (i >= NE) return;
    int s = ei[i];
    int d = ei[NE + i];
    s = max(0, min(s, NN - 1));
    d = max(0, min(d, NN - 1));
    int slot = atomicAdd(&g_cur[d], 1);
    g_srcs[slot] = s;
}

// ---------------------------------------------------------------------------
// CSR gather: out[n] = h[n] + sum_{src in csr[n]} h[src]
// ---------------------------------------------------------------------------
__global__ __launch_bounds__(256) void k_gather(const float4* __restrict__ h,
                                                float4* __restrict__ out) {
    int n = (blockIdx.x * blockDim.x + threadIdx.x) >> 5;
    if (n >= NN) return;
    int lane = threadIdx.x & 31;

    float4 a0 = h[n * 32 + lane];
    float4 a1 = make_float4(0.f, 0.f, 0.f, 0.f);
    float4 a2 = a1, a3 = a1;

    int e = g_row[n], end = g_row[n + 1];
    for (; e + 3 < end; e += 4) {
        int s0 = g_srcs[e], s1 = g_srcs[e + 1], s2 = g_srcs[e + 2], s3 = g_srcs[e + 3];
        float4 v0 = h[s0 * 32 + lane];
        float4 v1 = h[s1 * 32 + lane];
        float4 v2 = h[s2 * 32 + lane];
        float4 v3 = h[s3 * 32 + lane];
        a0.x += v0.x; a0.y += v0.y; a0.z += v0.z; a0.w += v0.w;
        a1.x += v1.x; a1.y += v1.y; a1.z += v1.z; a1.w += v1.w;
        a2.x += v2.x; a2.y += v2.y; a2.z += v2.z; a2.w += v2.w;
        a3.x += v3.x; a3.y += v3.y; a3.z += v3.z; a3.w += v3.w;
    }
    for (; e < end; e++) {
        int s0 = g_srcs[e];
        float4 v0 = h[s0 * 32 + lane];
        a0.x += v0.x; a0.y += v0.y; a0.z += v0.z; a0.w += v0.w;
    }
    float4 r;
    r.x = (a0.x + a1.x) + (a2.x + a3.x);
    r.y = (a0.y + a1.y) + (a2.y + a3.y);
    r.z = (a0.z + a1.z) + (a2.z + a3.z);
    r.w = (a0.w + a1.w) + (a2.w + a3.w);
    out[n * 32 + lane] = r;
}

// ---------------------------------------------------------------------------
// Fused double GEMM via 3xBF16 split (m16n8k16):
//   h'  = relu(A @ W1 + b1)   (accumulators -> re-split in regs -> smem)
//   out = relu(h' @ W2 + b2)
// W1,W2 hi/lo staged once per persistent block; 64-row A tiles streamed.
// ---------------------------------------------------------------------------
__device__ __forceinline__ void split_pack(float x, float y,
                                           unsigned& hi, unsigned& lo) {
    __nv_bfloat16 hx = __float2bfloat16(x);
    __nv_bfloat16 hy = __float2bfloat16(y);
    __nv_bfloat16 lx = __float2bfloat16(x - __bfloat162float(hx));
    __nv_bfloat16 ly = __float2bfloat16(y - __bfloat162float(hy));
    hi = ((unsigned)__bfloat16_as_ushort(hy) << 16) | __bfloat16_as_ushort(hx);
    lo = ((unsigned)__bfloat16_as_ushort(ly) << 16) | __bfloat16_as_ushort(lx);
}

__device__ __forceinline__ void mma16(float* d, unsigned a0, unsigned a1,
                                      unsigned a2, unsigned a3,
                                      unsigned b0, unsigned b1) {
    asm volatile(
        "mma.sync.aligned.m16n8k16.row.col.f32.bf16.bf16.f32 "
        "{%0,%1,%2,%3}, {%4,%5,%6,%7}, {%8,%9}, {%0,%1,%2,%3};"
        : "+f"(d[0]), "+f"(d[1]), "+f"(d[2]), "+f"(d[3])
        : "r"(a0), "r"(a1), "r"(a2), "r"(a3), "r"(b0), "r"(b1));
}

__device__ __forceinline__ void mma_phase(const unsigned* __restrict__ sWhi,
                                          const unsigned* __restrict__ sWlo,
                                          const unsigned* __restrict__ sAhi,
                                          const unsigned* __restrict__ sAlo,
                                          int rw, int nb, int quad, int tq,
                                          float acc[8][4]) {
#pragma unroll
    for (int i = 0; i < 8; i++)
#pragma unroll
        for (int j = 0; j < 4; j++) acc[i][j] = 0.f;

#pragma unroll
    for (int kk = 0; kk < 8; kk++) {
        int kp0 = kk * 8;
        const unsigned* pAh = sAhi + (rw + quad) * SA + kp0 + tq;
        const unsigned* pAl = sAlo + (rw + quad) * SA + kp0 + tq;
        unsigned ah0 = pAh[0];
        unsigned ah1 = pAh[8 * SA];
        unsigned ah2 = pAh[4];
        unsigned ah3 = pAh[8 * SA + 4];
        unsigned al0 = pAl[0];
        unsigned al1 = pAl[8 * SA];
        unsigned al2 = pAl[4];
        unsigned al3 = pAl[8 * SA + 4];

#pragma unroll
        for (int nt = 0; nt < 8; nt++) {
            int n0 = nb + nt * 8;
            const unsigned* pBh = sWhi + (n0 + quad) * SA + kp0 + tq;
            const unsigned* pBl = sWlo + (n0 + quad) * SA + kp0 + tq;
            unsigned bh0 = pBh[0];
            unsigned bh1 = pBh[4];
            unsigned bl0 = pBl[0];
            unsigned bl1 = pBl[4];
            mma16(acc[nt], ah0, ah1, ah2, ah3, bh0, bh1);
            mma16(acc[nt], ah0, ah1, ah2, ah3, bl0, bl1);
            mma16(acc[nt], al0, al1, al2, al3, bh0, bh1);
        }
    }
}

__global__ __launch_bounds__(256) void k_gemm2_bf3(const float* __restrict__ A,
                                                   const float* __restrict__ W1,
                                                   const float* __restrict__ b1,
                                                   const float* __restrict__ W2,
                                                   const float* __restrict__ b2,
                                                   float* __restrict__ out, int M) {
    extern __shared__ unsigned dyn[];
    unsigned* sW1hi = dyn;               // [128 n][64 kp] stride SA
    unsigned* sW1lo = sW1hi + 128 * SA;
    unsigned* sW2hi = sW1lo + 128 * SA;
    unsigned* sW2lo = sW2hi + 128 * SA;
    unsigned* sAhi  = sW2lo + 128 * SA;  // [64 r][64 kp] stride SA
    unsigned* sAlo  = sAhi + 64 * SA;

    int tid = threadIdx.x;

    // Stage W1, W2 hi/lo once
    for (int idx = tid; idx < 64 * 128; idx += 256) {
        int kp = idx >> 7, n = idx & 127;
        unsigned hi, lo;
        split_pack(W1[(2 * kp) * 128 + n], W1[(2 * kp + 1) * 128 + n], hi, lo);
        sW1hi[n * SA + kp] = hi;
        sW1lo[n * SA + kp] = lo;
        split_pack(W2[(2 * kp) * 128 + n], W2[(2 * kp + 1) * 128 + n], hi, lo);
        sW2hi[n * SA + kp] = hi;
        sW2lo[n * SA + kp] = lo;
    }
    __syncthreads();

    int lane = tid & 31;
    int w = tid >> 5;
    int rw = (w >> 1) * 16;
    int nb = (w & 1) * 64;
    int quad = lane >> 2, tq = lane & 3;

    float acc[8][4];

    int ntiles = (M + 63) / 64;
    for (int t = blockIdx.x; t < ntiles; t += gridDim.x) {
        int row0 = t * 64;

        // Stage A tile
        const float2* A2 = (const float2*)A;
        for (int idx = tid; idx < 64 * 64; idx += 256) {
            int r = idx >> 6, kp = idx & 63;
            float2 v = make_float2(0.f, 0.f);
            if (row0 + r < M) v = A2[(size_t)(row0 + r) * 64 + kp];
            unsigned hi, lo;
            split_pack(v.x, v.y, hi, lo);
            sAhi[r * SA + kp] = hi;
            sAlo[r * SA + kp] = lo;
        }
        __syncthreads();

        // Phase 1: acc = A @ W1
        mma_phase(sW1hi, sW1lo, sAhi, sAlo, rw, nb, quad, tq, acc);
        __syncthreads();                 // all reads of sA done

        // Mid epilogue: h' = relu(acc + b1) -> split -> smem A tile
        {
            int r0 = rw + quad, r1 = r0 + 8;
#pragma unroll
            for (int nt = 0; nt < 8; nt++) {
                int c0 = nb + nt * 8 + (tq << 1);
                float bx = b1[c0], by = b1[c0 + 1];
                int kp = c0 >> 1;
                unsigned hi, lo;
                split_pack(fmaxf(acc[nt][0] + bx, 0.f),
                           fmaxf(acc[nt][1] + by, 0.f), hi, lo);
                sAhi[r0 * SA + kp] = hi;
                sAlo[r0 * SA + kp] = lo;
                split_pack(fmaxf(acc[nt][2] + bx, 0.f),
                           fmaxf(acc[nt][3] + by, 0.f), hi, lo);
                sAhi[r1 * SA + kp] = hi;
                sAlo[r1 * SA + kp] = lo;
            }
        }
        __syncthreads();

        // Phase 2: acc = h' @ W2
        mma_phase(sW2hi, sW2lo, sAhi, sAlo, rw, nb, quad, tq, acc);

        // Final epilogue: out = relu(acc + b2)
        {
            int gr0 = row0 + rw + quad;
            int gr1 = gr0 + 8;
#pragma unroll
            for (int nt = 0; nt < 8; nt++) {
                int c0 = nb + nt * 8 + (tq << 1);
                float bx = b2[c0], by = b2[c0 + 1];
                if (gr0 < M) {
                    float2 o;
                    o.x = fmaxf(acc[nt][0] + bx, 0.f);
                    o.y = fmaxf(acc[nt][1] + by, 0.f);
                    *(float2*)(out + (size_t)gr0 * DD + c0) = o;
                }
                if (gr1 < M) {
                    float2 o;
                    o.x = fmaxf(acc[nt][2] + bx, 0.f);
                    o.y = fmaxf(acc[nt][3] + by, 0.f);
                    *(float2*)(out + (size_t)gr1 * DD + c0) = o;
                }
            }
        }
        __syncthreads();                 // before next tile overwrites sA
    }
}

// ---------------------------------------------------------------------------
// GraphNorm + ReLU, fused mean/var, 8-way unroll. 512 threads.
// ---------------------------------------------------------------------------
__global__ __launch_bounds__(512) void k_gnorm(const float* __restrict__ in,
                                               float* __restrict__ out,
                                               const float* __restrict__ w,
                                               const float* __restrict__ b,
                                               const float* __restrict__ ms) {
    __shared__ float redA[4][128];
    __shared__ float redB[4][128];
    int g = blockIdx.x;
    int d = threadIdx.x & 127;
    int sub = threadIdx.x >> 7;
    int st = g_start[g], cnt = g_cnt[g];
    if (cnt == 0) return;
    int end = st + cnt;

    float s1 = 0.f, s2 = 0.f;
    int r = st + sub;
    for (; r + 28 < end; r += 32) {
        float v0 = in[(size_t)(r)      * DD + d];
        float v1 = in[(size_t)(r + 4)  * DD + d];
        float v2 = in[(size_t)(r + 8)  * DD + d];
        float v3 = in[(size_t)(r + 12) * DD + d];
        float v4 = in[(size_t)(r + 16) * DD + d];
        float v5 = in[(size_t)(r + 20) * DD + d];
        float v6 = in[(size_t)(r + 24) * DD + d];
        float v7 = in[(size_t)(r + 28) * DD + d];
        s1 += ((v0 + v1) + (v2 + v3)) + ((v4 + v5) + (v6 + v7));
        s2 += ((v0 * v0 + v1 * v1) + (v2 * v2 + v3 * v3)) +
              ((v4 * v4 + v5 * v5) + (v6 * v6 + v7 * v7));
    }
    for (; r < end; r += 4) {
        float v = in[(size_t)r * DD + d];
        s1 += v;
        s2 += v * v;
    }
    redA[sub][d] = s1;
    redB[sub][d] = s2;
    __syncthreads();
    float S1 = (redA[0][d] + redA[1][d]) + (redA[2][d] + redA[3][d]);
    float S2 = (redB[0][d] + redB[1][d]) + (redB[2][d] + redB[3][d]);

    float inv_n = 1.0f / (float)cnt;
    float mh = S1 * inv_n;
    float m  = mh * ms[d];
    float var = S2 * inv_n - 2.f * m * mh + m * m;
    float sc = w[d] * rsqrtf(var + 1e-5f);
    float bd = b[d];

#pragma unroll 8
    for (r = st + sub; r < end; r += 4) {
        float v = in[(size_t)r * DD + d];
        out[(size_t)r * DD + d] = fmaxf((v - m) * sc + bd, 0.f);
    }
}

// ---------------------------------------------------------------------------
// Head: sum-pool per graph + MLP + log_softmax
// ---------------------------------------------------------------------------
__global__ __launch_bounds__(512) void k_head(const float* __restrict__ h,
                                              const float* __restrict__ fw1,
                                              const float* __restrict__ fb1,
                                              const float* __restrict__ fw2,
                                              const float* __restrict__ fb2,
                                              const float* __restrict__ fw3,
                                              const float* __restrict__ fb3,
                                              float* __restrict__ out) {
    int g = blockIdx.x;
    int d = threadIdx.x & 127;
    int sub = threadIdx.x >> 7;
    __shared__ float red[4][128];
    __shared__ float s0[128], s1[128], s2[128], lg[10];

    int st = g_start[g], cnt = g_cnt[g];
    int end = st + cnt;
    float p0 = 0.f, p1 = 0.f, p2 = 0.f, p3 = 0.f;
    int r = st + sub;
    for (; r + 12 < end; r += 16) {
        p0 += h[(size_t)(r)      * DD + d];
        p1 += h[(size_t)(r + 4)  * DD + d];
        p2 += h[(size_t)(r + 8)  * DD + d];
        p3 += h[(size_t)(r + 12) * DD + d];
    }
    for (; r < end; r += 4) p0 += h[(size_t)r * DD + d];
    red[sub][d] = (p0 + p1) + (p2 + p3);
    __syncthreads();
    if (sub == 0) s0[d] = (red[0][d] + red[1][d]) + (red[2][d] + red[3][d]);
    __syncthreads();

    if (sub == 0) {
        float acc = fb1[d];
        for (int k = 0; k < 128; k++) acc += s0[k] * fw1[k * 128 + d];
        s1[d] = fmaxf(acc, 0.f);
    }
    __syncthreads();

    if (sub == 0) {
        float acc = fb2[d];
        for (int k = 0; k < 128; k++) acc += s1[k] * fw2[k * 128 + d];
        s2[d] = fmaxf(acc, 0.f);
    }
    __syncthreads();

    if (sub == 0 && d < 10) {
        float a = fb3[d];
        for (int k = 0; k < 128; k++) a += s2[k] * fw3[k * 10 + d];
        lg[d] = a;
    }
    __syncthreads();

    if (threadIdx.x == 0) {
        float m = lg[0];
        for (int c = 1; c < 10; c++) m = fmaxf(m, lg[c]);
        float s = 0.f;
        for (int c = 0; c < 10; c++) s += expf(lg[c] - m);
        float lse = m + logf(s);
        for (int c = 0; c < 10; c++) out[g * 10 + c] = lg[c] - lse;
    }
}

// ---------------------------------------------------------------------------
extern "C" void kernel_launch(void* const* d_in, const int* in_sizes, int n_in,
                              void* d_out, int out_size) {
    const float* x      = (const float*)d_in[0];
    const float* gin_w1 = (const float*)d_in[1];
    const float* gin_b1 = (const float*)d_in[2];
    const float* gin_w2 = (const float*)d_in[3];
    const float* gin_b2 = (const float*)d_in[4];
    const float* gn_w   = (const float*)d_in[5];
    const float* gn_b   = (const float*)d_in[6];
    const float* gn_s   = (const float*)d_in[7];
    const float* fw1    = (const float*)d_in[8];
    const float* fb1    = (const float*)d_in[9];
    const float* fw2    = (const float*)d_in[10];
    const float* fb2    = (const float*)d_in[11];
    const float* fw3    = (const float*)d_in[12];
    const float* fb3    = (const float*)d_in[13];
    const int* ei    = (const int*)d_in[14];
    const int* batch = (const int*)d_in[15];
    float* out = (float*)d_out;

    float* bufA;  cudaGetSymbolAddress((void**)&bufA, g_bufA);
    float* bufB;  cudaGetSymbolAddress((void**)&bufB, g_bufB);

    cudaFuncSetAttribute(k_gemm2_bf3, cudaFuncAttributeMaxDynamicSharedMemorySize,
                         GEMM_SMEM);

    const int gath_grid = (NN * 32 + 255) / 256;

    // CSR build (once per launch)
    k_zero<<<(NN + 255) / 256, 256>>>();
    k_hist<<<(NE + 255) / 256, 256>>>(ei, batch);
    k_scan<<<1, 1024>>>();
    k_fill<<<(NE + 255) / 256, 256>>>(ei);

    const float* hin = x;
    for (int l = 0; l < NL; l++) {
        k_gather<<<gath_grid, 256>>>((const float4*)hin, (float4*)bufB);
        k_gemm2_bf3<<<148, 256, GEMM_SMEM>>>(bufB,
                                             gin_w1 + l * 128 * 128, gin_b1 + l * 128,
                                             gin_w2 + l * 128 * 128, gin_b2 + l * 128,
                                             bufB, NN);
        k_gnorm<<<NG, 512>>>(bufB, bufA, gn_w + l * 128, gn_b + l * 128,
                             gn_s + l * 128);
        hin = bufA;
    }

    k_head<<<NG, 512>>>(bufA, fw1, fb1, fw2, fb2, fw3, fb3, out);
}